// round 9
// baseline (speedup 1.0000x reference)
#include <cuda_runtime.h>
#include <math.h>
#include <stdint.h>

// Problem constants
#define BB   256
#define KIN  8
#define CC   1152
#define JJ   10
#define DD   16
#define JD   160
#define XKC  9216          // KIN*CC

// GEMM1: K=32 = 4 capsules x 8 kin per chunk
#define CB1  4
#define NCH1 288
// GEMM2: M=128 = 16 capsules x 8 kin; K=32 batch slice
#define CB2  16
#define NCH2 72

// smem FLOAT offsets: A-hi [4k8][32lane][9]f4, A-lo same, B [4k8][32lane][21]f4, cs
#define AHo  0
#define ALo  4608
#define BPo  9216
#define CSo  19968
#define SMEMB 82048        // bytes (>= 20480 floats for epilogue staging)

// ---------------------------------------------------------------------------
// Device globals (runtime allocation forbidden)
// ---------------------------------------------------------------------------
__device__ alignas(16) float g_spart[NCH1 * BB * JD];  // split-K partials (47MB)
__device__ alignas(16) float g_xt[XKC * BB];           // x transposed [kc][b]
__device__ alignas(16) float g_v[BB * JD];             // v[b][jd]
__device__ alignas(16) float g_b[CC * JJ];             // routing logits

__device__ __forceinline__ uint32_t tf32r(float f) {
    uint32_t u; asm("cvt.rna.tf32.f32 %0, %1;" : "=r"(u) : "f"(f)); return u;
}
__device__ __forceinline__ void hilo(float v, uint32_t& h, uint32_t& l) {
    h = tf32r(v);
    l = tf32r(v - __uint_as_float(h));
}
__device__ __forceinline__ void mma8(float* d, const uint32_t* a,
                                     uint32_t b0, uint32_t b1) {
    asm volatile(
        "mma.sync.aligned.m16n8k8.row.col.f32.tf32.tf32.f32 "
        "{%0,%1,%2,%3}, {%4,%5,%6,%7}, {%8,%9}, {%0,%1,%2,%3};"
        : "+f"(d[0]), "+f"(d[1]), "+f"(d[2]), "+f"(d[3])
        : "r"(a[0]), "r"(a[1]), "r"(a[2]), "r"(a[3]), "r"(b0), "r"(b1));
}

// ---------------------------------------------------------------------------
// Kernel T: transpose x -> g_xt[kc][b]
// ---------------------------------------------------------------------------
__global__ void __launch_bounds__(256) kernT(const float* __restrict__ x) {
    __shared__ float ts[32][33];
    int tx = threadIdx.x & 31, ty = threadIdx.x >> 5;
    int kc0 = blockIdx.x * 32, b0 = blockIdx.y * 32;
#pragma unroll
    for (int r = ty; r < 32; r += 8)
        ts[r][tx] = x[(size_t)(b0 + r) * XKC + kc0 + tx];
    __syncthreads();
#pragma unroll
    for (int r = ty; r < 32; r += 8)
        g_xt[(size_t)(kc0 + r) * BB + b0 + tx] = ts[tx][r];
}

// ---------------------------------------------------------------------------
// Core: M=128 x N=160 x K=32, tf32x3; fragments pre-staged in smem.
// A-frag f4 {A[m0][kc],A[m0+8][kc],A[m0][kc+4],A[m0+8][kc+4]} at [k8][lane][mt(9)]
// B-frag f4 {bh[kc][n],bh[kc+4][n],bl[kc][n],bl[kc+4][n]}     at [k8][lane][nt(21)]
// ---------------------------------------------------------------------------
__device__ __forceinline__ void gemm_core(const uint4* aH4, const uint4* aL4,
                                          const uint4* bb4, int tid,
                                          float d[20][4]) {
    int w = tid >> 5, lane = tid & 31;
#pragma unroll
    for (int nt = 0; nt < 20; nt++)
#pragma unroll
        for (int q = 0; q < 4; q++) d[nt][q] = 0.f;

#pragma unroll
    for (int k8 = 0; k8 < 4; k8++) {
        uint4 h = aH4[(k8 * 32 + lane) * 9 + w];
        uint4 l = aL4[(k8 * 32 + lane) * 9 + w];
        uint32_t A_h[4] = {h.x, h.y, h.z, h.w};
        uint32_t A_l[4] = {l.x, l.y, l.z, l.w};
        const uint4* bp = bb4 + (k8 * 32 + lane) * 21;
#pragma unroll
        for (int nt = 0; nt < 20; nt++) {
            uint4 bq = bp[nt];
            mma8(d[nt], A_h, bq.x, bq.y);   // hi*hi
            mma8(d[nt], A_h, bq.z, bq.w);   // hi*lo
            mma8(d[nt], A_l, bq.x, bq.y);   // lo*hi
        }
    }
}

// stage the block's 128x160 fp32 result into smem base
__device__ __forceinline__ void stage_tile(float* sm, int tid, float d[20][4]) {
    int w = tid >> 5, lane = tid & 31, g = lane >> 2, tig = lane & 3;
#pragma unroll
    for (int nt = 0; nt < 20; nt++) {
        *(float2*)(sm + (w * 16 + g) * JD + nt * 8 + 2 * tig) =
            make_float2(d[nt][0], d[nt][1]);
        *(float2*)(sm + (w * 16 + g + 8) * JD + nt * 8 + 2 * tig) =
            make_float2(d[nt][2], d[nt][3]);
    }
}

// ---------------------------------------------------------------------------
// Kernel B (GEMM1): s_part[chunk][b][jd]; grid (288, 2), block 256
// A = X[128b x 32k] (k = kin*4+cl), B = c_ij*W [32k x 160n]
// ---------------------------------------------------------------------------
__global__ void __launch_bounds__(256, 2) kernB(const float* __restrict__ x,
                                                const float* __restrict__ W) {
    extern __shared__ float sm[];
    uint4* aH4 = (uint4*)(sm + AHo);
    uint4* aL4 = (uint4*)(sm + ALo);
    uint4* bb4 = (uint4*)(sm + BPo);
    float* cs = sm + CSo;

    int tid = threadIdx.x;
    int c0 = blockIdx.x * CB1, b0 = blockIdx.y * 128;

    // softmax for 4 capsules
    if (tid < CB1 * JJ) {
        int cl = tid / 10, j = tid - cl * 10;
        const float* br = g_b + (size_t)(c0 + cl) * JJ;
        float bv[JJ], mx = -1e30f;
#pragma unroll
        for (int q = 0; q < JJ; q++) { bv[q] = br[q]; mx = fmaxf(mx, bv[q]); }
        float sum = 0.f;
#pragma unroll
        for (int q = 0; q < JJ; q++) { bv[q] = expf(bv[q] - mx); sum += bv[q]; }
        cs[tid] = bv[j] / sum;
    }

    // A fragments: (k8, lane, mt); kc = k8*8+tig; kin = kc>>2, cl = kc&3
    // kc+4 -> (kin+1, same cl); rows m0 = mt*16+g, m0+8
#pragma unroll
    for (int i = tid; i < 1024; i += 256) {
        int k8 = i >> 8, rem = i & 255, lane = rem >> 3, mt = rem & 7;
        int tig = lane & 3, g = lane >> 2;
        int kc = k8 * 8 + tig, kin = kc >> 2, cl = kc & 3;
        int m0 = mt * 16 + g;
        const float* xb = x + (size_t)(b0 + m0) * XKC + kin * CC + c0 + cl;
        uint4 h, l;
        hilo(xb[0], h.x, l.x);
        hilo(xb[8 * XKC], h.y, l.y);
        hilo(xb[CC], h.z, l.z);
        hilo(xb[8 * XKC + CC], h.w, l.w);
        aH4[(k8 * 32 + lane) * 9 + mt] = h;
        aL4[(k8 * 32 + lane) * 9 + mt] = l;
    }
    __syncthreads();   // cs ready

    // B fragments: (k8, lane, nt); n = nt*8+g; scale depends on (cl, n>>4)
#pragma unroll
    for (int i = tid; i < 2560; i += 256) {
        int k8 = i / 640, rem = i - k8 * 640, lane = rem / 20, nt = rem - lane * 20;
        int tig = lane & 3, g = lane >> 2;
        int kc = k8 * 8 + tig, kin = kc >> 2, cl = kc & 3;
        int n = nt * 8 + g;
        float sc = cs[cl * 10 + (n >> 4)];
        float2 wv = *(const float2*)(W + (size_t)(c0 + cl) * 1280 + n * 8 + kin);
        uint4 q;
        hilo(sc * wv.x, q.x, q.z);
        hilo(sc * wv.y, q.y, q.w);
        bb4[(k8 * 32 + lane) * 21 + nt] = q;
    }
    __syncthreads();

    float d[20][4];
    gemm_core(aH4, aL4, bb4, tid, d);

    __syncthreads();
    stage_tile(sm, tid, d);
    __syncthreads();

    float* dst = g_spart + (size_t)blockIdx.x * (BB * JD) + (size_t)b0 * JD;
#pragma unroll
    for (int i = tid; i < 128 * JD / 4; i += 256)
        ((float4*)dst)[i] = ((const float4*)sm)[i];
}

// ---------------------------------------------------------------------------
// Kernel C: reduce 288 split-K partials + squash -> g_v ; final iter -> d_out
// ---------------------------------------------------------------------------
__global__ void __launch_bounds__(512) kernC(float* __restrict__ out) {
    int idx = blockIdx.x * 512 + threadIdx.x;   // b*160 + jd
    float s = 1e-5f;                            // ref adds 1e-5 BEFORE magnitudes
    const float* sp = g_spart + idx;
#pragma unroll 8
    for (int ch = 0; ch < NCH1; ch++)
        s += sp[(size_t)ch * (BB * JD)];

    float mag = s * s;
#pragma unroll
    for (int off = 8; off; off >>= 1)
        mag += __shfl_xor_sync(0xffffffffu, mag, off, 16);

    float v = s * (mag / ((1.f + mag) * sqrtf(mag)));
    g_v[idx] = v;
    if (out) out[idx] = v;                      // (B,J,D,1) same linearization
}

// ---------------------------------------------------------------------------
// Kernel D (GEMM2): G[128r x 160jd] over a 32-batch slice, r = kin*16+cl,
// then contract with W -> atomicAdd b_ij. grid (72, 8), block 256
// ---------------------------------------------------------------------------
__global__ void __launch_bounds__(256, 2) kernD(const float* __restrict__ W) {
    extern __shared__ float sm[];
    uint4* aH4 = (uint4*)(sm + AHo);
    uint4* aL4 = (uint4*)(sm + ALo);
    uint4* bb4 = (uint4*)(sm + BPo);

    int tid = threadIdx.x;
    int c0 = blockIdx.x * CB2, b0 = blockIdx.y * 32;

    // A fragments: rows r = kin*16+cl (kin = mt; cl = g and g+8); cols = batch
#pragma unroll
    for (int i = tid; i < 1024; i += 256) {
        int k8 = i >> 8, rem = i & 255, lane = rem >> 3, mt = rem & 7;
        int tig = lane & 3, g = lane >> 2;
        int kc = k8 * 8 + tig;
        const float* x0 = g_xt + ((size_t)mt * CC + c0 + g) * BB + b0 + kc;
        const float* x1 = x0 + 8 * BB;    // cl = g+8
        uint4 h, l;
        hilo(x0[0], h.x, l.x);
        hilo(x1[0], h.y, l.y);
        hilo(x0[4], h.z, l.z);
        hilo(x1[4], h.w, l.w);
        aH4[(k8 * 32 + lane) * 9 + mt] = h;
        aL4[(k8 * 32 + lane) * 9 + mt] = l;
    }
    // B fragments: B[k][n] = v[b0+k][n]
#pragma unroll
    for (int i = tid; i < 2560; i += 256) {
        int k8 = i / 640, rem = i - k8 * 640, lane = rem / 20, nt = rem - lane * 20;
        int tig = lane & 3, g = lane >> 2;
        int kc = k8 * 8 + tig;
        int n = nt * 8 + g;
        uint4 q;
        hilo(g_v[(size_t)(b0 + kc) * JD + n], q.x, q.z);
        hilo(g_v[(size_t)(b0 + kc + 4) * JD + n], q.y, q.w);
        bb4[(k8 * 32 + lane) * 21 + nt] = q;
    }
    __syncthreads();

    float d[20][4];
    gemm_core(aH4, aL4, bb4, tid, d);

    __syncthreads();
    stage_tile(sm, tid, d);                     // G tile 128x160 at smem base
    __syncthreads();

    // agreement[c,j] = sum_{kin,d} W[c,j,d,kin] * G[(kin*16+cl)][(j*16+d)]
    if (tid < 160) {
        int cl = tid / 10, j = tid - cl * 10;
        const float* wr = W + (size_t)(c0 + cl) * 1280 + j * 128;
        float ag = 0.f;
#pragma unroll
        for (int kin = 0; kin < KIN; kin++)
#pragma unroll
            for (int d2 = 0; d2 < DD; d2++)
                ag = fmaf(wr[d2 * 8 + kin], sm[(kin * 16 + cl) * JD + j * 16 + d2], ag);
        atomicAdd(&g_b[(c0 + cl) * JJ + j], ag);
    }
}

// ---------------------------------------------------------------------------
// Host launcher (graph-capturable)
// ---------------------------------------------------------------------------
extern "C" void kernel_launch(void* const* d_in, const int* in_sizes, int n_in,
                              void* d_out, int out_size) {
    const float* x = (const float*)d_in[0];
    const float* W = (const float*)d_in[1];
    if (in_sizes[0] != BB * XKC) {   // defensive mapping by element count
        x = (const float*)d_in[1];
        W = (const float*)d_in[0];
    }

    cudaFuncSetAttribute(kernB, cudaFuncAttributeMaxDynamicSharedMemorySize, SMEMB);
    cudaFuncSetAttribute(kernD, cudaFuncAttributeMaxDynamicSharedMemorySize, SMEMB);

    void* pb = nullptr;
    cudaGetSymbolAddress(&pb, g_b);
    cudaMemsetAsync(pb, 0, CC * JJ * sizeof(float));   // b_ij = 0 each call

    kernT<<<dim3(XKC / 32, BB / 32), 256>>>(x);        // x -> g_xt

    dim3 gB(NCH1, 2);    // (288, 2)
    dim3 gD(NCH2, 8);    // (72, 8)
    for (int it = 0; it < 4; it++) {
        kernB<<<gB, 256, SMEMB>>>(x, W);                        // tensor GEMM1
        kernC<<<(BB * JD) / 512, 512>>>(it == 3 ? (float*)d_out : nullptr);
        if (it < 3)                                             // iter-4 agreement dead
            kernD<<<gD, 256, SMEMB>>>(W);                       // tensor GEMM2
    }
}

// round 10
// speedup vs baseline: 1.6337x; 1.6337x over previous
#include <cuda_runtime.h>
#include <math.h>
#include <stdint.h>

// Problem constants
#define BB   256
#define KIN  8
#define CC   1152
#define JJ   10
#define DD   16
#define JD   160
#define XKC  9216          // KIN*CC

// GEMM1: chunks of 8 capsules -> K=64 per block; 144 chunks
#define CB1  8
#define NCH1 144
// GEMM2: chunks of 16 capsules (M=128 rows), K=64 batch slice; 72 x 4
#define CB2  16
#define NCH2 72

#define SMEMB1 86336       // 8*32*21 uint4 (86016) + cs 320
#define SMEMB2 86016       // B frags; reused for G staging (81920)

// ---------------------------------------------------------------------------
// Device globals (runtime allocation forbidden)
// ---------------------------------------------------------------------------
__device__ alignas(16) float g_spart[NCH1 * BB * JD];   // split-K partials (23.6MB)
__device__ alignas(16) uint4 g_xf1h[NCH1 * 2 * 2048];   // GEMM1 A-frag hi (9.4MB)
__device__ alignas(16) uint4 g_xf1l[NCH1 * 2 * 2048];   // GEMM1 A-frag lo
__device__ alignas(16) uint4 g_xf2h[NCH2 * 4 * 2048];   // GEMM2 A-frag hi
__device__ alignas(16) uint4 g_xf2l[NCH2 * 4 * 2048];   // GEMM2 A-frag lo
__device__ alignas(16) float2 g_wf[NCH1 * 5120];        // W frag pairs (5.9MB)
__device__ alignas(16) uint4 g_vf[4 * 5120];            // v frags per b-slice (327KB)
__device__ alignas(16) float g_b[CC * JJ];              // routing logits

__device__ __forceinline__ uint32_t tf32r(float f) {
    uint32_t u; asm("cvt.rna.tf32.f32 %0, %1;" : "=r"(u) : "f"(f)); return u;
}
__device__ __forceinline__ void hilo(float v, uint32_t& h, uint32_t& l) {
    h = tf32r(v);
    l = tf32r(v - __uint_as_float(h));
}
__device__ __forceinline__ void mma8(float* d, const uint4& a,
                                     uint32_t b0, uint32_t b1) {
    asm volatile(
        "mma.sync.aligned.m16n8k8.row.col.f32.tf32.tf32.f32 "
        "{%0,%1,%2,%3}, {%4,%5,%6,%7}, {%8,%9}, {%0,%1,%2,%3};"
        : "+f"(d[0]), "+f"(d[1]), "+f"(d[2]), "+f"(d[3])
        : "r"(a.x), "r"(a.y), "r"(a.z), "r"(a.w), "r"(b0), "r"(b1));
}

// k-index mapping for GEMM1 (kc 0..63): cl = k8 (kc>>3), kin = 2*tig (+1 for kc+4)

// ---------------------------------------------------------------------------
// P1: GEMM1 A-fragments from x (once per call). grid (144,2), block 256.
// layout [chunk][half][w(8)][k8(8)][lane(32)]
// ---------------------------------------------------------------------------
__global__ void __launch_bounds__(256) prep1(const float* __restrict__ x) {
    int c0 = blockIdx.x * CB1, b0 = blockIdx.y * 128;
    size_t base = ((size_t)blockIdx.x * 2 + blockIdx.y) * 2048;
#pragma unroll
    for (int i = threadIdx.x; i < 2048; i += 256) {
        int w = i >> 8, k8 = (i >> 5) & 7, lane = i & 31;
        int tig = lane & 3, g = lane >> 2;
        int m0 = w * 16 + g;
        const float* xb = x + (size_t)(b0 + m0) * XKC + (2 * tig) * CC + c0 + k8;
        uint4 h, l;
        hilo(xb[0], h.x, l.x);              // A[m0][kc]
        hilo(xb[8 * XKC], h.y, l.y);        // A[m0+8][kc]
        hilo(xb[CC], h.z, l.z);             // A[m0][kc+4]  (kin+1)
        hilo(xb[8 * XKC + CC], h.w, l.w);   // A[m0+8][kc+4]
        g_xf1h[base + i] = h;
        g_xf1l[base + i] = l;
    }
}

// ---------------------------------------------------------------------------
// P2: GEMM2 A-fragments from x (once per call). grid (72,4), block 256.
// rows r = kin*16+cl (kin=w, cl=g / g+8); cols = batch kc = k8*8+tig (+4)
// ---------------------------------------------------------------------------
__global__ void __launch_bounds__(256) prep2(const float* __restrict__ x) {
    int c0 = blockIdx.x * CB2, b0 = blockIdx.y * 64;
    size_t base = ((size_t)blockIdx.x * 4 + blockIdx.y) * 2048;
#pragma unroll
    for (int i = threadIdx.x; i < 2048; i += 256) {
        int w = i >> 8, k8 = (i >> 5) & 7, lane = i & 31;
        int tig = lane & 3, g = lane >> 2;
        int kc = k8 * 8 + tig;
        const float* xb = x + (size_t)(b0 + kc) * XKC + w * CC + c0 + g;
        uint4 h, l;
        hilo(xb[0], h.x, l.x);              // A[m0][kc]   = XT[w*16+g][kc]
        hilo(xb[8], h.y, l.y);              // A[m0+8][kc] (cl = g+8)
        hilo(xb[4 * XKC], h.z, l.z);        // A[m0][kc+4]
        hilo(xb[4 * XKC + 8], h.w, l.w);    // A[m0+8][kc+4]
        g_xf2h[base + i] = h;
        g_xf2l[base + i] = l;
    }
}

// ---------------------------------------------------------------------------
// P3: W fragment pairs (once per call). grid 144, block 256.
// wf[chunk][k8][lane][nt] = (W[c0+k8, n, 2*tig], W[c0+k8, n, 2*tig+1])
// ---------------------------------------------------------------------------
__global__ void __launch_bounds__(256) prep3(const float* __restrict__ W) {
    int c0 = blockIdx.x * CB1;
    size_t base = (size_t)blockIdx.x * 5120;
#pragma unroll
    for (int i = threadIdx.x; i < 5120; i += 256) {
        int k8 = i / 640, rem = i - k8 * 640, lane = rem / 20, nt = rem - lane * 20;
        int tig = lane & 3, g = lane >> 2;
        int n = nt * 8 + g;
        g_wf[base + i] = *(const float2*)(
            W + (size_t)(c0 + k8) * 1280 + n * 8 + 2 * tig);
    }
}

// ---------------------------------------------------------------------------
// Core: M=128 x N=160 x K=64, tf32x3; A streamed from gmem frags (coalesced
// LDG.128), B fragments in smem (stride-21 uint4, conflict-free LDS.128).
// ---------------------------------------------------------------------------
__device__ __forceinline__ void gemm_core(const uint4* __restrict__ aH,
                                          const uint4* __restrict__ aL,
                                          const uint4* bb4, int tid,
                                          float d[20][4]) {
    int w = tid >> 5, lane = tid & 31;
#pragma unroll
    for (int nt = 0; nt < 20; nt++)
#pragma unroll
        for (int q = 0; q < 4; q++) d[nt][q] = 0.f;

    const uint4* ah = aH + w * 256 + lane;
    const uint4* al = aL + w * 256 + lane;
#pragma unroll
    for (int k8 = 0; k8 < 8; k8++) {
        uint4 h = ah[k8 * 32];
        uint4 l = al[k8 * 32];
        const uint4* bp = bb4 + (k8 * 32 + lane) * 21;
#pragma unroll
        for (int nt = 0; nt < 20; nt++) {
            uint4 bq = bp[nt];
            mma8(d[nt], h, bq.x, bq.y);   // hi*hi
            mma8(d[nt], h, bq.z, bq.w);   // hi*lo
            mma8(d[nt], l, bq.x, bq.y);   // lo*hi
        }
    }
}

// ---------------------------------------------------------------------------
// Kernel B (GEMM1): grid (144,2), block 256. B = c_ij*W from g_wf; epilogue
// stores fragments straight to g_spart (layout [chunk][b][n]).
// ---------------------------------------------------------------------------
__global__ void __launch_bounds__(256, 2) kernB(const float* __restrict__ dummy) {
    extern __shared__ float sm[];
    uint4* bb4 = (uint4*)sm;            // 5376 uint4
    float* cs = sm + 5376 * 4;          // 80 floats

    int tid = threadIdx.x;
    int chunk = blockIdx.x, half = blockIdx.y;
    int c0 = chunk * CB1;

    // softmax for 8 capsules
    if (tid < CB1 * JJ) {
        int cl = tid / 10, j = tid - cl * 10;
        const float* br = g_b + (size_t)(c0 + cl) * JJ;
        float bv[JJ], mx = -1e30f;
#pragma unroll
        for (int q = 0; q < JJ; q++) { bv[q] = br[q]; mx = fmaxf(mx, bv[q]); }
        float sum = 0.f;
#pragma unroll
        for (int q = 0; q < JJ; q++) { bv[q] = expf(bv[q] - mx); sum += bv[q]; }
        cs[tid] = bv[j] / sum;
    }
    __syncthreads();

    // B fragments: coalesced LDG.64 from g_wf, scale, hilo, STS.128
    const float2* wf = g_wf + (size_t)chunk * 5120;
#pragma unroll
    for (int i = tid; i < 5120; i += 256) {
        int k8 = i / 640, rem = i - k8 * 640, lane = rem / 20, nt = rem - lane * 20;
        int g = lane >> 2;
        float sc = cs[k8 * 10 + ((nt * 8 + g) >> 4)];   // cl = k8, j = n>>4
        float2 wv = wf[i];
        uint4 q;
        hilo(sc * wv.x, q.x, q.z);
        hilo(sc * wv.y, q.y, q.w);
        bb4[(k8 * 32 + lane) * 21 + nt] = q;
    }
    __syncthreads();

    const uint4* aH = g_xf1h + ((size_t)chunk * 2 + half) * 2048;
    const uint4* aL = g_xf1l + ((size_t)chunk * 2 + half) * 2048;
    float d[20][4];
    gemm_core(aH, aL, bb4, tid, d);

    // direct fragment store: d[nt][0..1] -> row m0, d[nt][2..3] -> row m0+8
    int w = tid >> 5, lane = tid & 31, g = lane >> 2, tig = lane & 3;
    float* dst = g_spart + ((size_t)chunk * BB + half * 128 + w * 16 + g) * JD
               + 2 * tig;
#pragma unroll
    for (int nt = 0; nt < 20; nt++) {
        *(float2*)(dst + nt * 8) = make_float2(d[nt][0], d[nt][1]);
        *(float2*)(dst + 8 * JD + nt * 8) = make_float2(d[nt][2], d[nt][3]);
    }
}

// ---------------------------------------------------------------------------
// Kernel C: reduce 144 split-K partials + squash; writes v-fragments g_vf
// (and d_out on the final iteration). grid 80, block 512.
// ---------------------------------------------------------------------------
__global__ void __launch_bounds__(512) kernC(float* __restrict__ out) {
    int idx = blockIdx.x * 512 + threadIdx.x;   // b*160 + n
    float s = 1e-5f;                            // ref adds 1e-5 BEFORE magnitudes
    const float* sp = g_spart + idx;
#pragma unroll 8
    for (int ch = 0; ch < NCH1; ch++)
        s += sp[(size_t)ch * (BB * JD)];

    float mag = s * s;
#pragma unroll
    for (int off = 8; off; off >>= 1)
        mag += __shfl_xor_sync(0xffffffffu, mag, off, 16);

    float v = s * (mag / ((1.f + mag) * sqrtf(mag)));

    // scatter v into fragment slots: slice = b>>6, kc = b&63
    int b = idx / JD, n = idx - b * JD;
    int slice = b >> 6, kc = b & 63;
    int k8 = kc >> 3, rr = kc & 7, tig = rr & 3, hf = rr >> 2;
    int lane = (n & 7) * 4 + tig, nt = n >> 3;
    uint32_t h, l;
    hilo(v, h, l);
    uint32_t* vq = (uint32_t*)&g_vf[(size_t)slice * 5120 + (k8 * 32 + lane) * 20 + nt];
    vq[hf] = h;          // .x (kc) or .y (kc+4)
    vq[2 + hf] = l;      // .z or .w

    if (out) out[idx] = v;                      // (B,J,D,1) same linearization
}

// ---------------------------------------------------------------------------
// Kernel D (GEMM2): G[128r x 160n] over 64-batch slice; agreement -> b_ij.
// grid (72,4), block 256.
// ---------------------------------------------------------------------------
__global__ void __launch_bounds__(256, 2) kernD(const float* __restrict__ W) {
    extern __shared__ float sm[];
    uint4* bb4 = (uint4*)sm;

    int tid = threadIdx.x;
    int chunk = blockIdx.x, slice = blockIdx.y;
    int c0 = chunk * CB2;

    // B fragments: pure coalesced copy from g_vf (pad stride 20 -> 21)
    const uint4* vf = g_vf + (size_t)slice * 5120;
#pragma unroll
    for (int i = tid; i < 5120; i += 256) {
        int k8 = i / 640, rem = i - k8 * 640, lane = rem / 20, nt = rem - lane * 20;
        bb4[(k8 * 32 + lane) * 21 + nt] = vf[i];
    }
    __syncthreads();

    const uint4* aH = g_xf2h + ((size_t)chunk * 4 + slice) * 2048;
    const uint4* aL = g_xf2l + ((size_t)chunk * 4 + slice) * 2048;
    float d[20][4];
    gemm_core(aH, aL, bb4, tid, d);

    __syncthreads();   // all warps done reading B before overwrite

    // stage G tile 128x160 into smem (reuses B region)
    int w = tid >> 5, lane = tid & 31, g = lane >> 2, tig = lane & 3;
#pragma unroll
    for (int nt = 0; nt < 20; nt++) {
        *(float2*)(sm + (w * 16 + g) * JD + nt * 8 + 2 * tig) =
            make_float2(d[nt][0], d[nt][1]);
        *(float2*)(sm + (w * 16 + g + 8) * JD + nt * 8 + 2 * tig) =
            make_float2(d[nt][2], d[nt][3]);
    }
    __syncthreads();

    // agreement[c,j] = sum_{kin,d} W[c,j,d,kin] * G[(kin*16+cl)][(j*16+d)]
    if (tid < 160) {
        int cl = tid / 10, j = tid - cl * 10;
        const float* wr = W + (size_t)(c0 + cl) * 1280 + j * 128;
        float ag = 0.f;
#pragma unroll
        for (int kin = 0; kin < KIN; kin++)
#pragma unroll
            for (int d2 = 0; d2 < DD; d2++)
                ag = fmaf(wr[d2 * 8 + kin], sm[(kin * 16 + cl) * JD + j * 16 + d2], ag);
        atomicAdd(&g_b[(c0 + cl) * JJ + j], ag);
    }
}

// ---------------------------------------------------------------------------
// Host launcher (graph-capturable)
// ---------------------------------------------------------------------------
extern "C" void kernel_launch(void* const* d_in, const int* in_sizes, int n_in,
                              void* d_out, int out_size) {
    const float* x = (const float*)d_in[0];
    const float* W = (const float*)d_in[1];
    if (in_sizes[0] != BB * XKC) {   // defensive mapping by element count
        x = (const float*)d_in[1];
        W = (const float*)d_in[0];
    }

    cudaFuncSetAttribute(kernB, cudaFuncAttributeMaxDynamicSharedMemorySize, SMEMB1);
    cudaFuncSetAttribute(kernD, cudaFuncAttributeMaxDynamicSharedMemorySize, SMEMB2);

    void* pb = nullptr;
    cudaGetSymbolAddress(&pb, g_b);
    cudaMemsetAsync(pb, 0, CC * JJ * sizeof(float));   // b_ij = 0 each call

    // one-time fragment preparation
    prep1<<<dim3(NCH1, 2), 256>>>(x);
    prep2<<<dim3(NCH2, 4), 256>>>(x);
    prep3<<<NCH1, 256>>>(W);

    dim3 gB(NCH1, 2);    // (144, 2)
    dim3 gD(NCH2, 4);    // (72, 4)
    for (int it = 0; it < 4; it++) {
        kernB<<<gB, 256, SMEMB1>>>(nullptr);                    // tensor GEMM1
        kernC<<<(BB * JD) / 512, 512>>>(it == 3 ? (float*)d_out : nullptr);
        if (it < 3)                                             // iter-4 agreement dead
            kernD<<<gD, 256, SMEMB2>>>(W);                      // tensor GEMM2
    }
}